// round 11
// baseline (speedup 1.0000x reference)
#include <cuda_runtime.h>
#include <cuda_fp16.h>
#include <cstdint>
#include <cstddef>

// ===================== problem sizes =====================
static constexpr int MM    = 8192;  // state_len (rows)
static constexpr int NN    = 8192;  // seq_len   (cols, softmax axis)
static constexpr int KK    = 1024;  // hidden
static constexpr int KTOT2 = 2048;  // compact storage: [hi | lo] per matrix

// ===================== GEMM config =====================
// CTA 128x128, 4 warps (2x2), warp tile 64x64, 3 stages, 96KB smem,
// 2 CTAs/SM, classic (non-persistent) launch. 48 logical K-chunks:
//   0-15 : ah x bh,  16-31 : al x bh,  32-47 : ah x bl
// mapped onto the compact [hi|lo] operand storage (hi stored once).
static constexpr int BM = 128, BN = 128, BK = 64;   // BK fp16 = 128B row
static constexpr int STAGES  = 3;
static constexpr int NCHUNK  = 48;
static constexpr int TILES_M = MM / BM;             // 64
static constexpr int TILES_N = NN / BN;             // 64
static constexpr int A_STAGE = BM * BK * 2;         // 16384
static constexpr int B_STAGE = BN * BK * 2;         // 16384
static constexpr int STAGE_BYTES = A_STAGE + B_STAGE;          // 32768
static constexpr int GEMM_SMEM   = STAGES * STAGE_BYTES;       // 98304
static constexpr int GEMM_THREADS = 128;            // 4 warps

// ===================== scratch (allocation-free) =====================
__device__ __half g_Ah[(size_t)MM * KTOT2];   // 32 MB  [ah | al]
__device__ __half g_Bh[(size_t)NN * KTOT2];   // 32 MB  [bh | bl]

// ===================== PTX helpers (base sm_100-safe) =====================
__device__ __forceinline__ uint32_t smem_to_u32(const void* p) {
    uint32_t a;
    asm("{ .reg .u64 t; cvta.to.shared.u64 t, %1; cvt.u32.u64 %0, t; }"
        : "=r"(a) : "l"(p));
    return a;
}

#define CP_ASYNC_16(dst, src) \
    asm volatile("cp.async.cg.shared.global [%0], [%1], 16;" \
                 :: "r"(dst), "l"(src) : "memory")
#define CP_COMMIT() \
    asm volatile("cp.async.commit_group;" ::: "memory")
#define CP_WAIT(n) \
    asm volatile("cp.async.wait_group %0;" :: "n"(n) : "memory")

#define LDSM_X4(r0, r1, r2, r3, addr) \
    asm volatile("ldmatrix.sync.aligned.m8n8.x4.shared.b16 {%0,%1,%2,%3}, [%4];" \
                 : "=r"(r0), "=r"(r1), "=r"(r2), "=r"(r3) : "r"(addr))

#define MMA16816(d, a, b) \
    asm volatile("mma.sync.aligned.m16n8k16.row.col.f32.f16.f16.f32 " \
                 "{%0,%1,%2,%3}, {%4,%5,%6,%7}, {%8,%9}, {%0,%1,%2,%3};" \
                 : "+f"((d)[0]), "+f"((d)[1]), "+f"((d)[2]), "+f"((d)[3]) \
                 : "r"((a)[0]), "r"((a)[1]), "r"((a)[2]), "r"((a)[3]), \
                   "r"((b)[0]), "r"((b)[1]))

// SW128-style XOR swizzle: 128B rows, 8 x 16B chunks; chunk' = chunk ^ (row & 7)
__device__ __forceinline__ uint32_t sw_off(int row, int chunk) {
    return (uint32_t)(row * 128 + (((chunk) ^ (row & 7)) << 4));
}

// K-chunk -> element offsets into the compact [hi|lo] operands
__device__ __forceinline__ int ka_of(int kc) {   // A: al for 16..31, else ah
    return (kc & 15) * BK + ((kc >= 16 && kc < 32) ? KK : 0);
}
__device__ __forceinline__ int kb_of(int kc) {   // B: bl for 32..47, else bh
    return (kc & 15) * BK + ((kc >= 32) ? KK : 0);
}

// ===================== kernel 1: fp32 -> fp16 split (compact) =====================
__device__ __forceinline__ void split2(float x, __half& h, __half& l) {
    h = __float2half_rn(x);
    l = __float2half_rn(x - __half2float(h));
}
__device__ __forceinline__ void st4h(__half* p, __half a, __half b, __half c, __half d) {
    __half2 lo = __halves2half2(a, b);
    __half2 hi = __halves2half2(c, d);
    uint2 u;
    u.x = *reinterpret_cast<uint32_t*>(&lo);
    u.y = *reinterpret_cast<uint32_t*>(&hi);
    *reinterpret_cast<uint2*>(p) = u;
}

__global__ void __launch_bounds__(256) convert_kernel(
    const float* __restrict__ A, const float* __restrict__ B,
    __half* __restrict__ Ah, __half* __restrict__ Bh)
{
    int idx = blockIdx.x * 256 + threadIdx.x;   // float4 index
    int i  = idx >> 8;                          // row (KK/4 = 256 float4 per row)
    int k4 = idx & 255;
    size_t base = (size_t)i * KTOT2 + (size_t)k4 * 4;

    float4 a = reinterpret_cast<const float4*>(A)[idx];
    float4 b = reinterpret_cast<const float4*>(B)[idx];

    __half ah0, al0, ah1, al1, ah2, al2, ah3, al3;
    split2(a.x, ah0, al0); split2(a.y, ah1, al1);
    split2(a.z, ah2, al2); split2(a.w, ah3, al3);
    st4h(Ah + base,      ah0, ah1, ah2, ah3);   // hi block
    st4h(Ah + base + KK, al0, al1, al2, al3);   // lo block

    __half bh0, bl0, bh1, bl1, bh2, bl2, bh3, bl3;
    split2(b.x, bh0, bl0); split2(b.y, bh1, bl1);
    split2(b.z, bh2, bl2); split2(b.w, bh3, bl3);
    st4h(Bh + base,      bh0, bh1, bh2, bh3);   // hi block
    st4h(Bh + base + KK, bl0, bl1, bl2, bl3);   // lo block
}

// ===================== kernel 2: mma.sync fp16 GEMM =====================
// out[m, n] = ah.bh + al.bh + ah.bl  (fp32), via 48 remapped K-chunks
__global__ void __launch_bounds__(GEMM_THREADS, 2)
gemm_kernel(const __half* __restrict__ Ah, const __half* __restrict__ Bh,
            float* __restrict__ out)
{
    extern __shared__ __align__(1024) char smem[];
    const uint32_t sb = smem_to_u32(smem);
    const int tid = threadIdx.x;
    const int wid = tid >> 5;
    const int lid = tid & 31;

    // supertile swizzle for L2 reuse: 8x8 groups
    constexpr int PER_G = 64;
    constexpr int GROUPS_N = TILES_N / 8;   // 8
    int id = blockIdx.x;
    int g = id / PER_G, r = id % PER_G;
    int tm = (g / GROUPS_N) * 8 + r / 8;
    int tn = (g % GROUPS_N) * 8 + r % 8;
    const int m0 = tm * BM, n0 = tn * BN;

    // warp layout: 2 (M) x 2 (N); warp tile 64 x 64
    const int wm = wid & 1;
    const int wn = wid >> 1;

    // cp.async assignment: 16B chunks; 128 threads cover 16 rows per pass
    const int lr = tid >> 3;       // base row (0..15)
    const int lc = tid & 7;        // chunk 0..7

    const __half* gA = Ah + (size_t)(m0 + lr) * KTOT2 + lc * 8;
    const __half* gB = Bh + (size_t)(n0 + lr) * KTOT2 + lc * 8;

    // accumulators: 4 m-tiles x 8 n-tiles x 4 floats = 128 regs
    float acc[4][8][4];
    #pragma unroll
    for (int i = 0; i < 4; i++)
        #pragma unroll
        for (int j = 0; j < 8; j++)
            #pragma unroll
            for (int q = 0; q < 4; q++) acc[i][j][q] = 0.f;

    // ---- load one stage of A+B via cp.async (8 A rows + 8 B rows per thread) ----
    auto load_stage = [&](int s, int kc) {
        uint32_t a_s = sb + s * STAGE_BYTES;
        uint32_t b_s = a_s + A_STAGE;
        const __half* ga = gA + ka_of(kc);
        const __half* gb = gB + kb_of(kc);
        #pragma unroll
        for (int i = 0; i < 8; i++) {
            CP_ASYNC_16(a_s + sw_off(lr + i * 16, lc), ga + (size_t)i * 16 * KTOT2);
            CP_ASYNC_16(b_s + sw_off(lr + i * 16, lc), gb + (size_t)i * 16 * KTOT2);
        }
    };

    // prologue: fill STAGES-1 stages
    #pragma unroll
    for (int s = 0; s < STAGES - 1; s++) {
        load_stage(s, s);
        CP_COMMIT();
    }

    // ldmatrix lane addressing (within a stage)
    const int a_row_l = wm * 64 + (lid & 15);
    const int a_chk_l = (lid >> 4);
    const int b_row_l = wn * 64 + (lid & 7) + ((lid >> 4) & 1) * 8;
    const int b_chk_l = (lid >> 3) & 1;

    auto load_af = [&](uint32_t a_s, int kk, uint32_t af[][4]) {
        #pragma unroll
        for (int mi = 0; mi < 4; mi++) {
            uint32_t addr = a_s + sw_off(a_row_l + mi * 16, kk * 2 + a_chk_l);
            LDSM_X4(af[mi][0], af[mi][1], af[mi][2], af[mi][3], addr);
        }
    };
    auto load_bf = [&](uint32_t b_s, int kk, uint32_t bf[][2]) {
        #pragma unroll
        for (int j2 = 0; j2 < 4; j2++) {
            uint32_t addr = b_s + sw_off(b_row_l + j2 * 16, kk * 2 + b_chk_l);
            uint32_t r0, r1, r2, r3;
            LDSM_X4(r0, r1, r2, r3, addr);
            bf[j2 * 2 + 0][0] = r0; bf[j2 * 2 + 0][1] = r1;
            bf[j2 * 2 + 1][0] = r2; bf[j2 * 2 + 1][1] = r3;
        }
    };

    for (int i = 0; i < NCHUNK; i++) {
        // stage i arrived; CP_WAIT must precede the barrier so every thread's
        // cp.async data for stage i is visible to every other thread's LDSM.
        CP_WAIT(STAGES - 2);
        __syncthreads();

        // refill the slot consumed at iter i-1 (ordered after the sync above)
        int j = i + STAGES - 1;
        if (j < NCHUNK) load_stage(j % STAGES, j);
        CP_COMMIT();

        const uint32_t a_s = sb + (i % STAGES) * STAGE_BYTES;
        const uint32_t b_s = a_s + A_STAGE;

        // software-pipelined fragments: LDSM for kk+1 overlaps MMA for kk
        uint32_t af[2][4][4];
        uint32_t bf[2][8][2];
        load_af(a_s, 0, af[0]);
        load_bf(b_s, 0, bf[0]);
        #pragma unroll
        for (int kk = 0; kk < 4; kk++) {
            int cur = kk & 1, nxt = cur ^ 1;
            if (kk < 3) {
                load_af(a_s, kk + 1, af[nxt]);
                load_bf(b_s, kk + 1, bf[nxt]);
            }
            #pragma unroll
            for (int mi = 0; mi < 4; mi++)
                #pragma unroll
                for (int nj = 0; nj < 8; nj++)
                    MMA16816(acc[mi][nj], af[cur][mi], bf[cur][nj]);
        }
        // no trailing sync: next iteration's CP_WAIT+sync orders slot reuse
    }

    // ---- epilogue: write fp32 accumulators ----
    const int er = lid >> 2;
    const int ec = (lid & 3) * 2;
    #pragma unroll
    for (int mi = 0; mi < 4; mi++) {
        int row = m0 + wm * 64 + mi * 16 + er;
        float* o0 = out + (size_t)row * NN + n0 + wn * 64 + ec;
        float* o1 = o0 + 8 * NN;
        #pragma unroll
        for (int nj = 0; nj < 8; nj++) {
            *reinterpret_cast<float2*>(o0 + nj * 8) =
                make_float2(acc[mi][nj][0], acc[mi][nj][1]);
            *reinterpret_cast<float2*>(o1 + nj * 8) =
                make_float2(acc[mi][nj][2], acc[mi][nj][3]);
        }
    }
}

// ===================== kernel 3: in-place row softmax =====================
__global__ void __launch_bounds__(256) softmax_kernel(float* __restrict__ out)
{
    __shared__ float smax[8];
    __shared__ float ssum[8];
    const int tid = threadIdx.x;
    float4* p = reinterpret_cast<float4*>(out + (size_t)blockIdx.x * NN);

    float4 v[8];
    #pragma unroll
    for (int j = 0; j < 8; j++) v[j] = p[tid + j * 256];

    float m = -1e30f;
    #pragma unroll
    for (int j = 0; j < 8; j++)
        m = fmaxf(m, fmaxf(fmaxf(v[j].x, v[j].y), fmaxf(v[j].z, v[j].w)));
    #pragma unroll
    for (int o = 16; o > 0; o >>= 1)
        m = fmaxf(m, __shfl_xor_sync(0xffffffffu, m, o));
    if ((tid & 31) == 0) smax[tid >> 5] = m;
    __syncthreads();
    m = smax[0];
    #pragma unroll
    for (int w = 1; w < 8; w++) m = fmaxf(m, smax[w]);

    float s = 0.f;
    #pragma unroll
    for (int j = 0; j < 8; j++) {
        v[j].x = __expf(v[j].x - m);
        v[j].y = __expf(v[j].y - m);
        v[j].z = __expf(v[j].z - m);
        v[j].w = __expf(v[j].w - m);
        s += v[j].x + v[j].y + v[j].z + v[j].w;
    }
    #pragma unroll
    for (int o = 16; o > 0; o >>= 1)
        s += __shfl_xor_sync(0xffffffffu, s, o);
    if ((tid & 31) == 0) ssum[tid >> 5] = s;
    __syncthreads();
    s = 0.f;
    #pragma unroll
    for (int w = 0; w < 8; w++) s += ssum[w];

    float inv = 1.0f / s;
    #pragma unroll
    for (int j = 0; j < 8; j++) {
        v[j].x *= inv; v[j].y *= inv; v[j].z *= inv; v[j].w *= inv;
        p[tid + j * 256] = v[j];
    }
}

// ===================== host launcher =====================
extern "C" void kernel_launch(void* const* d_in, const int* in_sizes, int n_in,
                              void* d_out, int out_size)
{
    const float* A = (const float*)d_in[0];   // out_state [8192, 1024]
    const float* B = (const float*)d_in[1];   // history   [8192, 1024]
    float* out = (float*)d_out;               // [8192, 8192] fp32

    void* pa = nullptr;
    void* pb = nullptr;
    cudaGetSymbolAddress(&pa, g_Ah);
    cudaGetSymbolAddress(&pb, g_Bh);

    // 1) split fp32 -> fp16 compact [hi|lo] operands
    convert_kernel<<<(MM * KK / 4) / 256, 256>>>(A, B, (__half*)pa, (__half*)pb);

    // 2) mma.sync GEMM -> energies into d_out
    static bool attr_set = false;
    if (!attr_set) {
        cudaFuncSetAttribute(gemm_kernel,
                             cudaFuncAttributeMaxDynamicSharedMemorySize, GEMM_SMEM);
        attr_set = true;
    }
    gemm_kernel<<<TILES_M * TILES_N, GEMM_THREADS, GEMM_SMEM>>>(
        (const __half*)pa, (const __half*)pb, out);

    // 3) in-place row softmax
    softmax_kernel<<<MM, 256>>>(out);
}

// round 14
// speedup vs baseline: 1.0017x; 1.0017x over previous
#include <cuda_runtime.h>
#include <cuda_fp16.h>
#include <cstdint>
#include <cstddef>

// ===================== problem sizes =====================
static constexpr int MM    = 8192;  // state_len (rows)
static constexpr int NN    = 8192;  // seq_len   (cols, softmax axis)
static constexpr int KK    = 1024;  // hidden
// compact storage [hi | lo] with 64-element pad to break the 4KB
// power-of-two row stride (4224B = 128 x 33 -> no L2-set/DRAM camping)
static constexpr int KPAD  = 64;
static constexpr int KROW  = 2 * KK + KPAD;   // 2112 elements per row

// ===================== GEMM config =====================
// CTA 128x128, 4 warps (2x2), warp tile 64x64, 3 stages, 96KB smem,
// 2 CTAs/SM, classic launch. 48 logical K-chunks:
//   0-15 : ah x bh,  16-31 : al x bh,  32-47 : ah x bl
static constexpr int BM = 128, BN = 128, BK = 64;   // BK fp16 = 128B row
static constexpr int STAGES  = 3;
static constexpr int NCHUNK  = 48;
static constexpr int TILES_M = MM / BM;             // 64
static constexpr int TILES_N = NN / BN;             // 64
static constexpr int A_STAGE = BM * BK * 2;         // 16384
static constexpr int B_STAGE = BN * BK * 2;         // 16384
static constexpr int STAGE_BYTES = A_STAGE + B_STAGE;          // 32768
static constexpr int GEMM_SMEM   = STAGES * STAGE_BYTES;       // 98304
static constexpr int GEMM_THREADS = 128;            // 4 warps

// ===================== scratch (allocation-free) =====================
__device__ __half g_Ah[(size_t)MM * KROW];   // ~34.6 MB  [ah | al | pad]
__device__ __half g_Bh[(size_t)NN * KROW];   // ~34.6 MB  [bh | bl | pad]

// ===================== PTX helpers (base sm_100-safe) =====================
__device__ __forceinline__ uint32_t smem_to_u32(const void* p) {
    uint32_t a;
    asm("{ .reg .u64 t; cvta.to.shared.u64 t, %1; cvt.u32.u64 %0, t; }"
        : "=r"(a) : "l"(p));
    return a;
}

#define CP_ASYNC_16(dst, src) \
    asm volatile("cp.async.cg.shared.global [%0], [%1], 16;" \
                 :: "r"(dst), "l"(src) : "memory")
#define CP_COMMIT() \
    asm volatile("cp.async.commit_group;" ::: "memory")
#define CP_WAIT(n) \
    asm volatile("cp.async.wait_group %0;" :: "n"(n) : "memory")

#define LDSM_X4(r0, r1, r2, r3, addr) \
    asm volatile("ldmatrix.sync.aligned.m8n8.x4.shared.b16 {%0,%1,%2,%3}, [%4];" \
                 : "=r"(r0), "=r"(r1), "=r"(r2), "=r"(r3) : "r"(addr))

#define MMA16816(d, a, b) \
    asm volatile("mma.sync.aligned.m16n8k16.row.col.f32.f16.f16.f32 " \
                 "{%0,%1,%2,%3}, {%4,%5,%6,%7}, {%8,%9}, {%0,%1,%2,%3};" \
                 : "+f"((d)[0]), "+f"((d)[1]), "+f"((d)[2]), "+f"((d)[3]) \
                 : "r"((a)[0]), "r"((a)[1]), "r"((a)[2]), "r"((a)[3]), \
                   "r"((b)[0]), "r"((b)[1]))

// SW128-style XOR swizzle: 128B rows, 8 x 16B chunks; chunk' = chunk ^ (row & 7)
__device__ __forceinline__ uint32_t sw_off(int row, int chunk) {
    return (uint32_t)(row * 128 + (((chunk) ^ (row & 7)) << 4));
}

// K-chunk -> element offsets into the compact [hi|lo] operands
__device__ __forceinline__ int ka_of(int kc) {   // A: al for 16..31, else ah
    return (kc & 15) * BK + ((kc >= 16 && kc < 32) ? KK : 0);
}
__device__ __forceinline__ int kb_of(int kc) {   // B: bl for 32..47, else bh
    return (kc & 15) * BK + ((kc >= 32) ? KK : 0);
}

// ===================== kernel 1: fp32 -> fp16 split (compact, padded) ==========
__device__ __forceinline__ void split2(float x, __half& h, __half& l) {
    h = __float2half_rn(x);
    l = __float2half_rn(x - __half2float(h));
}
__device__ __forceinline__ void st4h(__half* p, __half a, __half b, __half c, __half d) {
    __half2 lo = __halves2half2(a, b);
    __half2 hi = __halves2half2(c, d);
    uint2 u;
    u.x = *reinterpret_cast<uint32_t*>(&lo);
    u.y = *reinterpret_cast<uint32_t*>(&hi);
    *reinterpret_cast<uint2*>(p) = u;
}

__global__ void __launch_bounds__(256) convert_kernel(
    const float* __restrict__ A, const float* __restrict__ B,
    __half* __restrict__ Ah, __half* __restrict__ Bh)
{
    int idx = blockIdx.x * 256 + threadIdx.x;   // float4 index
    int i  = idx >> 8;                          // row (KK/4 = 256 float4 per row)
    int k4 = idx & 255;
    size_t base = (size_t)i * KROW + (size_t)k4 * 4;

    float4 a = reinterpret_cast<const float4*>(A)[idx];
    float4 b = reinterpret_cast<const float4*>(B)[idx];

    __half ah0, al0, ah1, al1, ah2, al2, ah3, al3;
    split2(a.x, ah0, al0); split2(a.y, ah1, al1);
    split2(a.z, ah2, al2); split2(a.w, ah3, al3);
    st4h(Ah + base,      ah0, ah1, ah2, ah3);   // hi block
    st4h(Ah + base + KK, al0, al1, al2, al3);   // lo block

    __half bh0, bl0, bh1, bl1, bh2, bl2, bh3, bl3;
    split2(b.x, bh0, bl0); split2(b.y, bh1, bl1);
    split2(b.z, bh2, bl2); split2(b.w, bh3, bl3);
    st4h(Bh + base,      bh0, bh1, bh2, bh3);   // hi block
    st4h(Bh + base + KK, bl0, bl1, bl2, bl3);   // lo block
}

// ===================== kernel 2: mma.sync fp16 GEMM =====================
// out[m, n] = ah.bh + al.bh + ah.bl  (fp32), via 48 remapped K-chunks
__global__ void __launch_bounds__(GEMM_THREADS, 2)
gemm_kernel(const __half* __restrict__ Ah, const __half* __restrict__ Bh,
            float* __restrict__ out)
{
    extern __shared__ __align__(1024) char smem[];
    const uint32_t sb = smem_to_u32(smem);
    const int tid = threadIdx.x;
    const int wid = tid >> 5;
    const int lid = tid & 31;

    // supertile swizzle for L2 reuse: 8x8 groups
    constexpr int PER_G = 64;
    constexpr int GROUPS_N = TILES_N / 8;   // 8
    int id = blockIdx.x;
    int g = id / PER_G, r = id % PER_G;
    int tm = (g / GROUPS_N) * 8 + r / 8;
    int tn = (g % GROUPS_N) * 8 + r % 8;
    const int m0 = tm * BM, n0 = tn * BN;

    // warp layout: 2 (M) x 2 (N); warp tile 64 x 64
    const int wm = wid & 1;
    const int wn = wid >> 1;

    // cp.async assignment: 16B chunks; 128 threads cover 16 rows per pass
    const int lr = tid >> 3;       // base row (0..15)
    const int lc = tid & 7;        // chunk 0..7

    const __half* gA = Ah + (size_t)(m0 + lr) * KROW + lc * 8;
    const __half* gB = Bh + (size_t)(n0 + lr) * KROW + lc * 8;

    // accumulators: 4 m-tiles x 8 n-tiles x 4 floats = 128 regs
    float acc[4][8][4];
    #pragma unroll
    for (int i = 0; i < 4; i++)
        #pragma unroll
        for (int j = 0; j < 8; j++)
            #pragma unroll
            for (int q = 0; q < 4; q++) acc[i][j][q] = 0.f;

    // ---- load one stage of A+B via cp.async (8 A rows + 8 B rows per thread) ----
    auto load_stage = [&](int s, int kc) {
        uint32_t a_s = sb + s * STAGE_BYTES;
        uint32_t b_s = a_s + A_STAGE;
        const __half* ga = gA + ka_of(kc);
        const __half* gb = gB + kb_of(kc);
        #pragma unroll
        for (int i = 0; i < 8; i++) {
            CP_ASYNC_16(a_s + sw_off(lr + i * 16, lc), ga + (size_t)i * 16 * KROW);
            CP_ASYNC_16(b_s + sw_off(lr + i * 16, lc), gb + (size_t)i * 16 * KROW);
        }
    };

    // prologue: fill STAGES-1 stages
    #pragma unroll
    for (int s = 0; s < STAGES - 1; s++) {
        load_stage(s, s);
        CP_COMMIT();
    }

    // ldmatrix lane addressing (within a stage)
    const int a_row_l = wm * 64 + (lid & 15);
    const int a_chk_l = (lid >> 4);
    const int b_row_l = wn * 64 + (lid & 7) + ((lid >> 4) & 1) * 8;
    const int b_chk_l = (lid >> 3) & 1;

    auto load_af = [&](uint32_t a_s, int kk, uint32_t af[][4]) {
        #pragma unroll
        for (int mi = 0; mi < 4; mi++) {
            uint32_t addr = a_s + sw_off(a_row_l + mi * 16, kk * 2 + a_chk_l);
            LDSM_X4(af[mi][0], af[mi][1], af[mi][2], af[mi][3], addr);
        }
    };
    auto load_bf = [&](uint32_t b_s, int kk, uint32_t bf[][2]) {
        #pragma unroll
        for (int j2 = 0; j2 < 4; j2++) {
            uint32_t addr = b_s + sw_off(b_row_l + j2 * 16, kk * 2 + b_chk_l);
            uint32_t r0, r1, r2, r3;
            LDSM_X4(r0, r1, r2, r3, addr);
            bf[j2 * 2 + 0][0] = r0; bf[j2 * 2 + 0][1] = r1;
            bf[j2 * 2 + 1][0] = r2; bf[j2 * 2 + 1][1] = r3;
        }
    };

    for (int i = 0; i < NCHUNK; i++) {
        // stage i arrived; CP_WAIT must precede the barrier so every thread's
        // cp.async data for stage i is visible to every other thread's LDSM.
        CP_WAIT(STAGES - 2);
        __syncthreads();

        // refill the slot consumed at iter i-1 (ordered after the sync above)
        int j = i + STAGES - 1;
        if (j < NCHUNK) load_stage(j % STAGES, j);
        CP_COMMIT();

        const uint32_t a_s = sb + (i % STAGES) * STAGE_BYTES;
        const uint32_t b_s = a_s + A_STAGE;

        // software-pipelined fragments: LDSM for kk+1 overlaps MMA for kk
        uint32_t af[2][4][4];
        uint32_t bf[2][8][2];
        load_af(a_s, 0, af[0]);
        load_bf(b_s, 0, bf[0]);
        #pragma unroll
        for (int kk = 0; kk < 4; kk++) {
            int cur = kk & 1, nxt = cur ^ 1;
            if (kk < 3) {
                load_af(a_s, kk + 1, af[nxt]);
                load_bf(b_s, kk + 1, bf[nxt]);
            }
            #pragma unroll
            for (int mi = 0; mi < 4; mi++)
                #pragma unroll
                for (int nj = 0; nj < 8; nj++)
                    MMA16816(acc[mi][nj], af[cur][mi], bf[cur][nj]);
        }
        // no trailing sync: next iteration's CP_WAIT+sync orders slot reuse
    }

    // ---- epilogue: write fp32 accumulators ----
    const int er = lid >> 2;
    const int ec = (lid & 3) * 2;
    #pragma unroll
    for (int mi = 0; mi < 4; mi++) {
        int row = m0 + wm * 64 + mi * 16 + er;
        float* o0 = out + (size_t)row * NN + n0 + wn * 64 + ec;
        float* o1 = o0 + 8 * NN;
        #pragma unroll
        for (int nj = 0; nj < 8; nj++) {
            *reinterpret_cast<float2*>(o0 + nj * 8) =
                make_float2(acc[mi][nj][0], acc[mi][nj][1]);
            *reinterpret_cast<float2*>(o1 + nj * 8) =
                make_float2(acc[mi][nj][2], acc[mi][nj][3]);
        }
    }
}

// ===================== kernel 3: in-place row softmax =====================
__global__ void __launch_bounds__(256) softmax_kernel(float* __restrict__ out)
{
    __shared__ float smax[8];
    __shared__ float ssum[8];
    const int tid = threadIdx.x;
    float4* p = reinterpret_cast<float4*>(out + (size_t)blockIdx.x * NN);

    float4 v[8];
    #pragma unroll
    for (int j = 0; j < 8; j++) v[j] = p[tid + j * 256];

    float m = -1e30f;
    #pragma unroll
    for (int j = 0; j < 8; j++)
        m = fmaxf(m, fmaxf(fmaxf(v[j].x, v[j].y), fmaxf(v[j].z, v[j].w)));
    #pragma unroll
    for (int o = 16; o > 0; o >>= 1)
        m = fmaxf(m, __shfl_xor_sync(0xffffffffu, m, o));
    if ((tid & 31) == 0) smax[tid >> 5] = m;
    __syncthreads();
    m = smax[0];
    #pragma unroll
    for (int w = 1; w < 8; w++) m = fmaxf(m, smax[w]);

    float s = 0.f;
    #pragma unroll
    for (int j = 0; j < 8; j++) {
        v[j].x = __expf(v[j].x - m);
        v[j].y = __expf(v[j].y - m);
        v[j].z = __expf(v[j].z - m);
        v[j].w = __expf(v[j].w - m);
        s += v[j].x + v[j].y + v[j].z + v[j].w;
    }
    #pragma unroll
    for (int o = 16; o > 0; o >>= 1)
        s += __shfl_xor_sync(0xffffffffu, s, o);
    if ((tid & 31) == 0) ssum[tid >> 5] = s;
    __syncthreads();
    s = 0.f;
    #pragma unroll
    for (int w = 0; w < 8; w++) s += ssum[w];

    float inv = 1.0f / s;
    #pragma unroll
    for (int j = 0; j < 8; j++) {
        v[j].x *= inv; v[j].y *= inv; v[j].z *= inv; v[j].w *= inv;
        p[tid + j * 256] = v[j];
    }
}

// ===================== host launcher =====================
extern "C" void kernel_launch(void* const* d_in, const int* in_sizes, int n_in,
                              void* d_out, int out_size)
{
    const float* A = (const float*)d_in[0];   // out_state [8192, 1024]
    const float* B = (const float*)d_in[1];   // history   [8192, 1024]
    float* out = (float*)d_out;               // [8192, 8192] fp32

    void* pa = nullptr;
    void* pb = nullptr;
    cudaGetSymbolAddress(&pa, g_Ah);
    cudaGetSymbolAddress(&pb, g_Bh);

    // 1) split fp32 -> fp16 compact padded [hi|lo] operands
    convert_kernel<<<(MM * KK / 4) / 256, 256>>>(A, B, (__half*)pa, (__half*)pb);

    // 2) mma.sync GEMM -> energies into d_out
    static bool attr_set = false;
    if (!attr_set) {
        cudaFuncSetAttribute(gemm_kernel,
                             cudaFuncAttributeMaxDynamicSharedMemorySize, GEMM_SMEM);
        attr_set = true;
    }
    gemm_kernel<<<TILES_M * TILES_N, GEMM_THREADS, GEMM_SMEM>>>(
        (const __half*)pa, (const __half*)pb, out);

    // 3) in-place row softmax
    softmax_kernel<<<MM, 256>>>(out);
}

// round 16
// speedup vs baseline: 1.0110x; 1.0092x over previous
#include <cuda_runtime.h>
#include <cuda_fp16.h>
#include <cstdint>
#include <cstddef>

// ===================== problem sizes =====================
static constexpr int MM   = 8192;   // state_len (rows)
static constexpr int NN   = 8192;   // seq_len   (cols, softmax axis)
static constexpr int KK   = 1024;   // hidden
static constexpr int KTOT = 3072;   // 3*KK : [hi*hi | lo*hi | hi*lo]

// ===================== GEMM config =====================
// FROZEN best configuration (R8, 1052.9us): CTA 128x128, 4 warps (2x2),
// warp tile 64x64, 3 stages, 96KB smem -> 2 CTAs/SM, classic launch,
// single __syncthreads per K-chunk, [hi|lo|hi]x[hi|hi|lo] 3-block operands.
static constexpr int BM = 128, BN = 128, BK = 64;   // BK fp16 = 128B row
static constexpr int STAGES  = 3;
static constexpr int NCHUNK  = KTOT / BK;           // 48
static constexpr int TILES_M = MM / BM;             // 64
static constexpr int TILES_N = NN / BN;             // 64
static constexpr int A_STAGE = BM * BK * 2;         // 16384
static constexpr int B_STAGE = BN * BK * 2;         // 16384
static constexpr int STAGE_BYTES = A_STAGE + B_STAGE;          // 32768
static constexpr int GEMM_SMEM   = STAGES * STAGE_BYTES;       // 98304
static constexpr int GEMM_THREADS = 128;            // 4 warps

// ===================== scratch (allocation-free) =====================
__device__ __half g_Ah[(size_t)MM * KTOT];   // 48 MB
__device__ __half g_Bh[(size_t)NN * KTOT];   // 48 MB

// ===================== PTX helpers (base sm_100-safe) =====================
__device__ __forceinline__ uint32_t smem_to_u32(const void* p) {
    uint32_t a;
    asm("{ .reg .u64 t; cvta.to.shared.u64 t, %1; cvt.u32.u64 %0, t; }"
        : "=r"(a) : "l"(p));
    return a;
}

#define CP_ASYNC_16(dst, src) \
    asm volatile("cp.async.cg.shared.global [%0], [%1], 16;" \
                 :: "r"(dst), "l"(src) : "memory")
#define CP_COMMIT() \
    asm volatile("cp.async.commit_group;" ::: "memory")
#define CP_WAIT(n) \
    asm volatile("cp.async.wait_group %0;" :: "n"(n) : "memory")

#define LDSM_X4(r0, r1, r2, r3, addr) \
    asm volatile("ldmatrix.sync.aligned.m8n8.x4.shared.b16 {%0,%1,%2,%3}, [%4];" \
                 : "=r"(r0), "=r"(r1), "=r"(r2), "=r"(r3) : "r"(addr))

#define MMA16816(d, a, b) \
    asm volatile("mma.sync.aligned.m16n8k16.row.col.f32.f16.f16.f32 " \
                 "{%0,%1,%2,%3}, {%4,%5,%6,%7}, {%8,%9}, {%0,%1,%2,%3};" \
                 : "+f"((d)[0]), "+f"((d)[1]), "+f"((d)[2]), "+f"((d)[3]) \
                 : "r"((a)[0]), "r"((a)[1]), "r"((a)[2]), "r"((a)[3]), \
                   "r"((b)[0]), "r"((b)[1]))

// SW128-style XOR swizzle: 128B rows, 8 x 16B chunks; chunk' = chunk ^ (row & 7)
__device__ __forceinline__ uint32_t sw_off(int row, int chunk) {
    return (uint32_t)(row * 128 + (((chunk) ^ (row & 7)) << 4));
}

// ===================== kernel 1: fp32 -> fp16 3-way split =====================
__device__ __forceinline__ void split2(float x, __half& h, __half& l) {
    h = __float2half_rn(x);
    l = __float2half_rn(x - __half2float(h));
}
__device__ __forceinline__ void st4h(__half* p, __half a, __half b, __half c, __half d) {
    __half2 lo = __halves2half2(a, b);
    __half2 hi = __halves2half2(c, d);
    uint2 u;
    u.x = *reinterpret_cast<uint32_t*>(&lo);
    u.y = *reinterpret_cast<uint32_t*>(&hi);
    *reinterpret_cast<uint2*>(p) = u;
}

__global__ void __launch_bounds__(256) convert_kernel(
    const float* __restrict__ A, const float* __restrict__ B,
    __half* __restrict__ Ah, __half* __restrict__ Bh)
{
    int idx = blockIdx.x * 256 + threadIdx.x;   // float4 index
    int i  = idx >> 8;                          // row (KK/4 = 256 float4 per row)
    int k4 = idx & 255;
    size_t base = (size_t)i * KTOT + (size_t)k4 * 4;

    float4 a = reinterpret_cast<const float4*>(A)[idx];
    float4 b = reinterpret_cast<const float4*>(B)[idx];

    __half ah0, al0, ah1, al1, ah2, al2, ah3, al3;
    split2(a.x, ah0, al0); split2(a.y, ah1, al1);
    split2(a.z, ah2, al2); split2(a.w, ah3, al3);
    st4h(Ah + base,          ah0, ah1, ah2, ah3);   // hi
    st4h(Ah + base + KK,     al0, al1, al2, al3);   // lo
    st4h(Ah + base + 2 * KK, ah0, ah1, ah2, ah3);   // hi

    __half bh0, bl0, bh1, bl1, bh2, bl2, bh3, bl3;
    split2(b.x, bh0, bl0); split2(b.y, bh1, bl1);
    split2(b.z, bh2, bl2); split2(b.w, bh3, bl3);
    st4h(Bh + base,          bh0, bh1, bh2, bh3);   // hi
    st4h(Bh + base + KK,     bh0, bh1, bh2, bh3);   // hi
    st4h(Bh + base + 2 * KK, bl0, bl1, bl2, bl3);   // lo
}

// ===================== kernel 2: mma.sync fp16 GEMM =====================
// out[m, n] = sum_k A'[m,k] * B'[n,k]   (fp32)
// CTA tile 128x128, 4 warps (2M x 2N), warp tile 64x64. 2 CTAs/SM.
__global__ void __launch_bounds__(GEMM_THREADS, 2)
gemm_kernel(const __half* __restrict__ Ah, const __half* __restrict__ Bh,
            float* __restrict__ out)
{
    extern __shared__ __align__(1024) char smem[];
    const uint32_t sb = smem_to_u32(smem);
    const int tid = threadIdx.x;
    const int wid = tid >> 5;
    const int lid = tid & 31;

    // supertile swizzle for L2 reuse: 8x8 groups
    constexpr int PER_G = 64;
    constexpr int GROUPS_N = TILES_N / 8;   // 8
    int id = blockIdx.x;
    int g = id / PER_G, r = id % PER_G;
    int tm = (g / GROUPS_N) * 8 + r / 8;
    int tn = (g % GROUPS_N) * 8 + r % 8;
    const int m0 = tm * BM, n0 = tn * BN;

    // warp layout: 2 (M) x 2 (N); warp tile 64 x 64
    const int wm = wid & 1;
    const int wn = wid >> 1;

    // cp.async assignment: 16B chunks; 128 threads cover 16 rows per pass
    const int lr = tid >> 3;       // base row (0..15)
    const int lc = tid & 7;        // chunk 0..7

    const __half* gA = Ah + (size_t)(m0 + lr) * KTOT + lc * 8;
    const __half* gB = Bh + (size_t)(n0 + lr) * KTOT + lc * 8;

    // accumulators: 4 m-tiles x 8 n-tiles x 4 floats = 128 regs
    float acc[4][8][4];
    #pragma unroll
    for (int i = 0; i < 4; i++)
        #pragma unroll
        for (int j = 0; j < 8; j++)
            #pragma unroll
            for (int q = 0; q < 4; q++) acc[i][j][q] = 0.f;

    // ---- load one stage of A+B via cp.async (8 A rows + 8 B rows per thread) ----
    auto load_stage = [&](int s, int kc) {
        uint32_t a_s = sb + s * STAGE_BYTES;
        uint32_t b_s = a_s + A_STAGE;
        const __half* ga = gA + (size_t)kc * BK;
        const __half* gb = gB + (size_t)kc * BK;
        #pragma unroll
        for (int i = 0; i < 8; i++) {
            CP_ASYNC_16(a_s + sw_off(lr + i * 16, lc), ga + (size_t)i * 16 * KTOT);
            CP_ASYNC_16(b_s + sw_off(lr + i * 16, lc), gb + (size_t)i * 16 * KTOT);
        }
    };

    // prologue: fill STAGES-1 stages
    #pragma unroll
    for (int s = 0; s < STAGES - 1; s++) {
        load_stage(s, s);
        CP_COMMIT();
    }

    // ldmatrix lane addressing (within a stage)
    const int a_row_l = wm * 64 + (lid & 15);
    const int a_chk_l = (lid >> 4);
    const int b_row_l = wn * 64 + (lid & 7) + ((lid >> 4) & 1) * 8;
    const int b_chk_l = (lid >> 3) & 1;

    auto load_af = [&](uint32_t a_s, int kk, uint32_t af[][4]) {
        #pragma unroll
        for (int mi = 0; mi < 4; mi++) {
            uint32_t addr = a_s + sw_off(a_row_l + mi * 16, kk * 2 + a_chk_l);
            LDSM_X4(af[mi][0], af[mi][1], af[mi][2], af[mi][3], addr);
        }
    };
    auto load_bf = [&](uint32_t b_s, int kk, uint32_t bf[][2]) {
        #pragma unroll
        for (int j2 = 0; j2 < 4; j2++) {
            uint32_t addr = b_s + sw_off(b_row_l + j2 * 16, kk * 2 + b_chk_l);
            uint32_t r0, r1, r2, r3;
            LDSM_X4(r0, r1, r2, r3, addr);
            bf[j2 * 2 + 0][0] = r0; bf[j2 * 2 + 0][1] = r1;
            bf[j2 * 2 + 1][0] = r2; bf[j2 * 2 + 1][1] = r3;
        }
    };

    for (int i = 0; i < NCHUNK; i++) {
        // stage i arrived; CP_WAIT must precede the barrier so every thread's
        // cp.async data for stage i is visible to every other thread's LDSM.
        CP_WAIT(STAGES - 2);
        __syncthreads();

        // refill the slot consumed at iter i-1 (ordered after the sync above)
        int j = i + STAGES - 1;
        if (j < NCHUNK) load_stage(j % STAGES, j);
        CP_COMMIT();

        const uint32_t a_s = sb + (i % STAGES) * STAGE_BYTES;
        const uint32_t b_s = a_s + A_STAGE;

        // software-pipelined fragments: LDSM for kk+1 overlaps MMA for kk
        uint32_t af[2][4][4];
        uint32_t bf[2][8][2];
        load_af(a_s, 0, af[0]);
        load_bf(b_s, 0, bf[0]);
        #pragma unroll
        for (int kk = 0; kk < 4; kk++) {
            int cur = kk & 1, nxt = cur ^ 1;
            if (kk < 3) {
                load_af(a_s, kk + 1, af[nxt]);
                load_bf(b_s, kk + 1, bf[nxt]);
            }
            #pragma unroll
            for (int mi = 0; mi < 4; mi++)
                #pragma unroll
                for (int nj = 0; nj < 8; nj++)
                    MMA16816(acc[mi][nj], af[cur][mi], bf[cur][nj]);
        }
        // no trailing sync: next iteration's CP_WAIT+sync orders slot reuse
    }

    // ---- epilogue: write fp32 accumulators ----
    const int er = lid >> 2;
    const int ec = (lid & 3) * 2;
    #pragma unroll
    for (int mi = 0; mi < 4; mi++) {
        int row = m0 + wm * 64 + mi * 16 + er;
        float* o0 = out + (size_t)row * NN + n0 + wn * 64 + ec;
        float* o1 = o0 + 8 * NN;
        #pragma unroll
        for (int nj = 0; nj < 8; nj++) {
            *reinterpret_cast<float2*>(o0 + nj * 8) =
                make_float2(acc[mi][nj][0], acc[mi][nj][1]);
            *reinterpret_cast<float2*>(o1 + nj * 8) =
                make_float2(acc[mi][nj][2], acc[mi][nj][3]);
        }
    }
}

// ===================== kernel 3: in-place row softmax =====================
__global__ void __launch_bounds__(256) softmax_kernel(float* __restrict__ out)
{
    __shared__ float smax[8];
    __shared__ float ssum[8];
    const int tid = threadIdx.x;
    float4* p = reinterpret_cast<float4*>(out + (size_t)blockIdx.x * NN);

    float4 v[8];
    #pragma unroll
    for (int j = 0; j < 8; j++) v[j] = p[tid + j * 256];

    float m = -1e30f;
    #pragma unroll
    for (int j = 0; j < 8; j++)
        m = fmaxf(m, fmaxf(fmaxf(v[j].x, v[j].y), fmaxf(v[j].z, v[j].w)));
    #pragma unroll
    for (int o = 16; o > 0; o >>= 1)
        m = fmaxf(m, __shfl_xor_sync(0xffffffffu, m, o));
    if ((tid & 31) == 0) smax[tid >> 5] = m;
    __syncthreads();
    m = smax[0];
    #pragma unroll
    for (int w = 1; w < 8; w++) m = fmaxf(m, smax[w]);

    float s = 0.f;
    #pragma unroll
    for (int j = 0; j < 8; j++) {
        v[j].x = __expf(v[j].x - m);
        v[j].y = __expf(v[j].y - m);
        v[j].z = __expf(v[j].z - m);
        v[j].w = __expf(v[j].w - m);
        s += v[j].x + v[j].y + v[j].z + v[j].w;
    }
    #pragma unroll
    for (int o = 16; o > 0; o >>= 1)
        s += __shfl_xor_sync(0xffffffffu, s, o);
    if ((tid & 31) == 0) ssum[tid >> 5] = s;
    __syncthreads();
    s = 0.f;
    #pragma unroll
    for (int w = 0; w < 8; w++) s += ssum[w];

    float inv = 1.0f / s;
    #pragma unroll
    for (int j = 0; j < 8; j++) {
        v[j].x *= inv; v[j].y *= inv; v[j].z *= inv; v[j].w *= inv;
        p[tid + j * 256] = v[j];
    }
}

// ===================== host launcher =====================
extern "C" void kernel_launch(void* const* d_in, const int* in_sizes, int n_in,
                              void* d_out, int out_size)
{
    const float* A = (const float*)d_in[0];   // out_state [8192, 1024]
    const float* B = (const float*)d_in[1];   // history   [8192, 1024]
    float* out = (float*)d_out;               // [8192, 8192] fp32

    void* pa = nullptr;
    void* pb = nullptr;
    cudaGetSymbolAddress(&pa, g_Ah);
    cudaGetSymbolAddress(&pb, g_Bh);

    // 1) split fp32 -> fp16 augmented operands
    convert_kernel<<<(MM * KK / 4) / 256, 256>>>(A, B, (__half*)pa, (__half*)pb);

    // 2) mma.sync GEMM -> energies into d_out
    static bool attr_set = false;
    if (!attr_set) {
        cudaFuncSetAttribute(gemm_kernel,
                             cudaFuncAttributeMaxDynamicSharedMemorySize, GEMM_SMEM);
        attr_set = true;
    }
    gemm_kernel<<<TILES_M * TILES_N, GEMM_THREADS, GEMM_SMEM>>>(
        (const __half*)pa, (const __half*)pb, out);

    // 3) in-place row softmax
    softmax_kernel<<<MM, 256>>>(out);
}